// round 9
// baseline (speedup 1.0000x reference)
#include <cuda_runtime.h>
#include <cuda_fp16.h>
#include <math.h>
#include <stdint.h>

#define BATCH   2
#define SEQ     2048
#define DMODEL  4096
#define NHEADS  32
#define NKV     8
#define HD      128
#define QKVD    6144            // (32 + 2*8) * 128
#define MTOK    (BATCH * SEQ)   // 4096

// Scratch (allocation-free rule: __device__ globals)
__device__ __half g_qkvh [(size_t)MTOK * QKVD];
__device__ __half g_Xh   [(size_t)MTOK * DMODEL];
__device__ __half g_WqTh [(size_t)QKVD * DMODEL];
__device__ __half g_WoTh [(size_t)DMODEL * DMODEL];
__device__ __half g_Qh   [(size_t)BATCH * NHEADS * SEQ * HD];
__device__ __half g_Kh   [(size_t)BATCH * NKV * SEQ * HD];
__device__ __half g_Vt   [(size_t)BATCH * NKV * HD * SEQ];
__device__ __half g_attnH[(size_t)MTOK * DMODEL];

// ---------------------------------------------------------------------------
// Helpers (baseline PTX only)
// ---------------------------------------------------------------------------
__device__ __forceinline__ uint32_t s2u(const void* p) {
    uint32_t a;
    asm("{ .reg .u64 t; cvta.to.shared.u64 t, %1; cvt.u32.u64 %0, t; }"
        : "=r"(a) : "l"(p));
    return a;
}
__device__ __forceinline__ void cp_async16(uint32_t dst, const void* src) {
    asm volatile("cp.async.cg.shared.global [%0], [%1], 16;"
                 :: "r"(dst), "l"(src) : "memory");
}
__device__ __forceinline__ void mma_f16(float* c, const uint32_t* a,
                                        const uint32_t* b) {
    asm volatile(
        "mma.sync.aligned.m16n8k16.row.col.f32.f16.f16.f32 "
        "{%0,%1,%2,%3}, {%4,%5,%6,%7}, {%8,%9}, {%0,%1,%2,%3};"
        : "+f"(c[0]), "+f"(c[1]), "+f"(c[2]), "+f"(c[3])
        : "r"(a[0]), "r"(a[1]), "r"(a[2]), "r"(a[3]), "r"(b[0]), "r"(b[1]));
}
__device__ __forceinline__ void ldm4(uint32_t& r0, uint32_t& r1,
                                     uint32_t& r2, uint32_t& r3, uint32_t addr) {
    asm volatile("ldmatrix.sync.aligned.m8n8.x4.shared.b16 {%0,%1,%2,%3}, [%4];"
                 : "=r"(r0), "=r"(r1), "=r"(r2), "=r"(r3) : "r"(addr));
}
__device__ __forceinline__ uint32_t packh2(float x, float y) {
    __half2 h = __floats2half2_rn(x, y);
    return *(uint32_t*)&h;
}

// ---------------------------------------------------------------------------
// Prep kernels
// ---------------------------------------------------------------------------
__global__ void f32_to_f16_kernel(const float4* __restrict__ in,
                                  __half2* __restrict__ out, int n4) {
    for (int i = blockIdx.x * blockDim.x + threadIdx.x; i < n4;
         i += gridDim.x * blockDim.x) {
        float4 v = in[i];
        out[2 * i]     = __floats2half2_rn(v.x, v.y);
        out[2 * i + 1] = __floats2half2_rn(v.z, v.w);
    }
}

__global__ void transpose_f16_kernel(const float* __restrict__ in,
                                     __half* __restrict__ out, int R, int C) {
    __shared__ float t[32][33];
    int cb = blockIdx.x * 32, rb = blockIdx.y * 32;
    int tx = threadIdx.x, ty = threadIdx.y;
    #pragma unroll
    for (int i = 0; i < 4; i++)
        t[ty + i * 8][tx] = in[(size_t)(rb + ty + i * 8) * C + cb + tx];
    __syncthreads();
    #pragma unroll
    for (int i = 0; i < 4; i++)
        out[(size_t)(cb + ty + i * 8) * R + rb + tx] =
            __float2half_rn(t[tx][ty + i * 8]);
}

// ---------------------------------------------------------------------------
// fp16 mma.sync GEMM: C[M,N] = A[M,K] @ Bt[N,K]^T   (fp16, K-major)
// CTA tile 256x128, BK=32, 256 thr = 8 warps (4M x 2N), warp tile 64x64.
// ldmatrix frag fetch, 3-stage cp.async pipeline. HALF_OUT selects C dtype.
// ---------------------------------------------------------------------------
#define GLD   40                                  // smem stride in halves
#define GA_B  (256 * GLD * 2)                     // A bytes per stage (20480)
#define GB_B  (128 * GLD * 2)                     // B bytes per stage (10240)
#define GSTG  (GA_B + GB_B)                       // 30720
#define GEMM_SMEM (3 * GSTG)                      // 92160

template<bool HALF_OUT>
__global__ __launch_bounds__(256, 1) void gemm_mma_f16(
    const __half* __restrict__ A, const __half* __restrict__ Bt,
    void* __restrict__ Cv, int N, int K)
{
    extern __shared__ char dsm[];
    const int tid  = threadIdx.x;
    const int wid  = tid >> 5;
    const int lane = tid & 31;
    const int gid  = lane >> 2;
    const int tig  = lane & 3;
    const int wm   = (wid >> 1) * 64;   // 4 M-warp slots
    const int wn   = (wid & 1) * 64;    // 2 N-warp slots
    const int m0 = blockIdx.y * 256;
    const int n0 = blockIdx.x * 128;
    const uint32_t sb = s2u(dsm);

    const int lrow = ((lane >> 3) & 1) * 8 + (lane & 7);
    const int lcol = (lane >> 4) * 8;

    const __half* Ab = A  + (size_t)m0 * K;
    const __half* Bb = Bt + (size_t)n0 * K;
    const int NC = K >> 5;

    #define GLOAD(kc, st)                                                      \
    {                                                                          \
        uint32_t sbase = sb + (st) * GSTG;                                     \
        _Pragma("unroll")                                                      \
        for (int i = 0; i < 4; i++) {                                          \
            int idx = i * 256 + tid;                                           \
            int r = idx >> 2, c8 = idx & 3;                                    \
            cp_async16(sbase + (uint32_t)(r * GLD + c8 * 8) * 2,               \
                       Ab + (size_t)r * K + (kc) * 32 + c8 * 8);               \
        }                                                                      \
        _Pragma("unroll")                                                      \
        for (int i = 0; i < 2; i++) {                                          \
            int idx = i * 256 + tid;                                           \
            int r = idx >> 2, c8 = idx & 3;                                    \
            cp_async16(sbase + GA_B + (uint32_t)(r * GLD + c8 * 8) * 2,        \
                       Bb + (size_t)r * K + (kc) * 32 + c8 * 8);               \
        }                                                                      \
        asm volatile("cp.async.commit_group;" ::: "memory");                   \
    }

    float acc[4][8][4];
    #pragma unroll
    for (int mi = 0; mi < 4; mi++)
        #pragma unroll
        for (int ni = 0; ni < 8; ni++)
            #pragma unroll
            for (int q = 0; q < 4; q++) acc[mi][ni][q] = 0.f;

    GLOAD(0, 0);
    GLOAD(1, 1);

    for (int kc = 0; kc < NC; kc++) {
        if (kc + 1 < NC) asm volatile("cp.async.wait_group 1;" ::: "memory");
        else             asm volatile("cp.async.wait_group 0;" ::: "memory");
        __syncthreads();
        if (kc + 2 < NC) GLOAD(kc + 2, (kc + 2) % 3);

        const uint32_t sA = sb + (kc % 3) * GSTG;
        const uint32_t sB = sA + GA_B;

        #pragma unroll
        for (int ks = 0; ks < 2; ks++) {
            const int k0h = ks * 16;
            uint32_t af[4][4], bf[8][2];
            #pragma unroll
            for (int mi = 0; mi < 4; mi++)
                ldm4(af[mi][0], af[mi][1], af[mi][2], af[mi][3],
                     sA + (uint32_t)((wm + mi * 16 + lrow) * GLD + k0h + lcol) * 2);
            #pragma unroll
            for (int np = 0; np < 4; np++) {
                uint32_t r0, r1, r2, r3;
                ldm4(r0, r1, r2, r3,
                     sB + (uint32_t)((wn + np * 16 + lrow) * GLD + k0h + lcol) * 2);
                bf[2 * np][0] = r0;     bf[2 * np][1] = r2;
                bf[2 * np + 1][0] = r1; bf[2 * np + 1][1] = r3;
            }
            #pragma unroll
            for (int mi = 0; mi < 4; mi++)
                #pragma unroll
                for (int ni = 0; ni < 8; ni++)
                    mma_f16(acc[mi][ni], af[mi], bf[ni]);
        }
    }

    #pragma unroll
    for (int mi = 0; mi < 4; mi++) {
        const int r0 = m0 + wm + mi * 16 + gid;
        #pragma unroll
        for (int ni = 0; ni < 8; ni++) {
            const int c = n0 + wn + ni * 8 + 2 * tig;
            if (HALF_OUT) {
                __half* C = (__half*)Cv;
                *(__half2*)(C + (size_t)r0 * N + c) =
                    __floats2half2_rn(acc[mi][ni][0], acc[mi][ni][1]);
                *(__half2*)(C + (size_t)(r0 + 8) * N + c) =
                    __floats2half2_rn(acc[mi][ni][2], acc[mi][ni][3]);
            } else {
                float* C = (float*)Cv;
                *(float2*)(C + (size_t)r0 * N + c) =
                    make_float2(acc[mi][ni][0], acc[mi][ni][1]);
                *(float2*)(C + (size_t)(r0 + 8) * N + c) =
                    make_float2(acc[mi][ni][2], acc[mi][ni][3]);
            }
        }
    }
}

// ---------------------------------------------------------------------------
// RoPE + pack: fp16 qkv -> fp16 Qh [b][h][s][d], Kh [b][kv][s][d]
// ---------------------------------------------------------------------------
__global__ void rope_pack_kernel(const __half* __restrict__ qkv,
                                 const float* __restrict__ cosT,
                                 const float* __restrict__ sinT,
                                 __half* __restrict__ Qh,
                                 __half* __restrict__ Kh)
{
    const int token = blockIdx.x;
    const int head  = blockIdx.y;   // 0..39
    const int b = token >> 11;
    const int s = token & (SEQ - 1);
    const int d = threadIdx.x;      // 0..63

    const __half* p = qkv + (size_t)token * QKVD + head * HD;
    const float c  = cosT[s * HD + d];
    const float sn = sinT[s * HD + d];
    const float x1 = __half2float(p[d]);
    const float x2 = __half2float(p[d + 64]);
    const float o1 = x1 * c - x2 * sn;
    const float o2 = x2 * c + x1 * sn;

    __half* dst = (head < NHEADS)
        ? Qh + ((size_t)(b * NHEADS + head) * SEQ + s) * HD
        : Kh + ((size_t)(b * NKV + head - NHEADS) * SEQ + s) * HD;
    dst[d]      = __float2half_rn(o1);
    dst[d + 64] = __float2half_rn(o2);
}

// V pack: fp16 qkv V region -> fp16 transposed Vt [b][kv][d][s]
__global__ void v_pack_kernel(const __half* __restrict__ qkv,
                              __half* __restrict__ Vt)
{
    __shared__ __half t[32][34];
    const int sx = blockIdx.x * 32;
    const int dy = blockIdx.y * 32;
    const int bkv = blockIdx.z;
    const int b = bkv >> 3, kvh = bkv & 7;
    const int tx = threadIdx.x, ty = threadIdx.y;

    #pragma unroll
    for (int i = 0; i < 4; i++)
        t[ty + i * 8][tx] = qkv[(size_t)(b * SEQ + sx + ty + i * 8) * QKVD +
                                (NHEADS + NKV) * HD + kvh * HD + dy + tx];
    __syncthreads();
    #pragma unroll
    for (int i = 0; i < 4; i++)
        Vt[((size_t)(b * NKV + kvh) * HD + dy + ty + i * 8) * SEQ + sx + tx] =
            t[tx][ty + i * 8];
}

// ---------------------------------------------------------------------------
// Flash attention, mma.sync fp16, ldmatrix fragment fetch.
// BQ=128, BK=64, 256 thr = 8 warps, warp owns 16 q rows.
// ---------------------------------------------------------------------------
#define QLD 136
#define KLD 136
#define VLD 72
#define K_TILE_B (64 * KLD * 2)
#define V_TILE_B (128 * VLD * 2)
#define STAGE_B  (K_TILE_B + V_TILE_B)
#define FLASH_SMEM (2 * STAGE_B)

__global__ __launch_bounds__(256) void flash_mma(
    const __half* __restrict__ Qh, const __half* __restrict__ Kh,
    const __half* __restrict__ Vt, __half* __restrict__ attnH)
{
    extern __shared__ char dsm[];
    const int tid = threadIdx.x;
    const int wid = tid >> 5, lane = tid & 31;
    const int gid = lane >> 2, tig = lane & 3;
    const int lrow = ((lane >> 3) & 1) * 8 + (lane & 7);
    const int lcol = (lane >> 4) * 8;
    const int qt = (gridDim.x - 1) - blockIdx.x;
    const int bh = blockIdx.y;
    const int b = bh >> 5, h = bh & 31, kvh = h >> 2;
    const int q0 = qt * 128;
    const uint32_t sb = s2u(dsm);
    const float scale = 0.08838834764831845f;

    const __half* Qg = Qh + ((size_t)(b * NHEADS + h) * SEQ + q0) * HD;
    const __half* Kg = Kh + (size_t)(b * NKV + kvh) * SEQ * HD;
    const __half* Vg = Vt + (size_t)(b * NKV + kvh) * HD * SEQ;

    #pragma unroll
    for (int i = 0; i < 8; i++) {
        int idx = i * 256 + tid;
        int r = idx >> 4, c = idx & 15;
        cp_async16(sb + (uint32_t)(r * QLD + c * 8) * 2,
                   Qg + (size_t)r * HD + c * 8);
    }
    asm volatile("cp.async.commit_group;" ::: "memory");
    asm volatile("cp.async.wait_group 0;" ::: "memory");
    __syncthreads();

    uint32_t qf[8][4];
    #pragma unroll
    for (int kk = 0; kk < 8; kk++)
        ldm4(qf[kk][0], qf[kk][1], qf[kk][2], qf[kk][3],
             sb + (uint32_t)((wid * 16 + lrow) * QLD + kk * 16 + lcol) * 2);
    __syncthreads();

    #define LOADKV(kt, st)                                                     \
    {                                                                          \
        const int k0_ = (kt) * 64;                                             \
        uint32_t base_ = sb + (st) * STAGE_B;                                  \
        _Pragma("unroll")                                                      \
        for (int i_ = 0; i_ < 4; i_++) {                                       \
            int idx_ = i_ * 256 + tid;                                         \
            int r_ = idx_ >> 4, c_ = idx_ & 15;                                \
            cp_async16(base_ + (uint32_t)(r_ * KLD + c_ * 8) * 2,              \
                       Kg + (size_t)(k0_ + r_) * HD + c_ * 8);                 \
        }                                                                      \
        _Pragma("unroll")                                                      \
        for (int i_ = 0; i_ < 4; i_++) {                                       \
            int idx_ = i_ * 256 + tid;                                         \
            int d_ = idx_ >> 3, c_ = idx_ & 7;                                 \
            cp_async16(base_ + K_TILE_B + (uint32_t)(d_ * VLD + c_ * 8) * 2,   \
                       Vg + (size_t)d_ * SEQ + k0_ + c_ * 8);                  \
        }                                                                      \
        asm volatile("cp.async.commit_group;" ::: "memory");                   \
    }

    float Of[16][4];
    #pragma unroll
    for (int ni = 0; ni < 16; ni++)
        #pragma unroll
        for (int q = 0; q < 4; q++) Of[ni][q] = 0.f;
    float m0 = -INFINITY, m1 = -INFINITY, l0 = 0.f, l1 = 0.f;
    const int nkt = 2 * qt + 2;

    LOADKV(0, 0);

    for (int kt = 0; kt < nkt; kt++) {
        const int s = kt & 1;
        asm volatile("cp.async.wait_group 0;" ::: "memory");
        __syncthreads();
        if (kt + 1 < nkt) LOADKV(kt + 1, s ^ 1);

        const uint32_t kbase = sb + s * STAGE_B;
        const uint32_t vbase = kbase + K_TILE_B;
        const int k0 = kt * 64;

        float S[8][4];
        #pragma unroll
        for (int ni = 0; ni < 8; ni++)
            S[ni][0] = S[ni][1] = S[ni][2] = S[ni][3] = 0.f;
        #pragma unroll
        for (int np = 0; np < 4; np++) {
            #pragma unroll
            for (int kk = 0; kk < 8; kk++) {
                uint32_t r0, r1, r2, r3;
                ldm4(r0, r1, r2, r3,
                     kbase + (uint32_t)((np * 16 + lrow) * KLD + kk * 16 + lcol) * 2);
                uint32_t b0[2] = {r0, r2}, b1[2] = {r1, r3};
                mma_f16(S[2 * np],     qf[kk], b0);
                mma_f16(S[2 * np + 1], qf[kk], b1);
            }
        }

        const int row0 = q0 + wid * 16 + gid, row1 = row0 + 8;
        #pragma unroll
        for (int ni = 0; ni < 8; ni++) {
            const int col = k0 + ni * 8 + 2 * tig;
            S[ni][0] = (col     <= row0) ? S[ni][0] * scale : -1e30f;
            S[ni][1] = (col + 1 <= row0) ? S[ni][1] * scale : -1e30f;
            S[ni][2] = (col     <= row1) ? S[ni][2] * scale : -1e30f;
            S[ni][3] = (col + 1 <= row1) ? S[ni][3] * scale : -1e30f;
        }

        float mx0 = fmaxf(S[0][0], S[0][1]), mx1 = fmaxf(S[0][2], S[0][3]);
        #pragma unroll
        for (int ni = 1; ni < 8; ni++) {
            mx0 = fmaxf(mx0, fmaxf(S[ni][0], S[ni][1]));
            mx1 = fmaxf(mx1, fmaxf(S[ni][2], S[ni][3]));
        }
        mx0 = fmaxf(mx0, __shfl_xor_sync(0xFFFFFFFFu, mx0, 1));
        mx0 = fmaxf(mx0, __shfl_xor_sync(0xFFFFFFFFu, mx0, 2));
        mx1 = fmaxf(mx1, __shfl_xor_sync(0xFFFFFFFFu, mx1, 1));
        mx1 = fmaxf(mx1, __shfl_xor_sync(0xFFFFFFFFu, mx1, 2));
        const float mn0 = fmaxf(m0, mx0), mn1 = fmaxf(m1, mx1);
        const float a0 = __expf(m0 - mn0), a1 = __expf(m1 - mn1);
        float s0 = 0.f, s1 = 0.f;
        #pragma unroll
        for (int ni = 0; ni < 8; ni++) {
            S[ni][0] = __expf(S[ni][0] - mn0);
            S[ni][1] = __expf(S[ni][1] - mn0);
            S[ni][2] = __expf(S[ni][2] - mn1);
            S[ni][3] = __expf(S[ni][3] - mn1);
            s0 += S[ni][0] + S[ni][1];
            s1 += S[ni][2] + S[ni][3];
        }
        s0 += __shfl_xor_sync(0xFFFFFFFFu, s0, 1);
        s0 += __shfl_xor_sync(0xFFFFFFFFu, s0, 2);
        s1 += __shfl_xor_sync(0xFFFFFFFFu, s1, 1);
        s1 += __shfl_xor_sync(0xFFFFFFFFu, s1, 2);
        l0 = l0 * a0 + s0;  l1 = l1 * a1 + s1;
        m0 = mn0;  m1 = mn1;

        #pragma unroll
        for (int ni = 0; ni < 16; ni++) {
            Of[ni][0] *= a0; Of[ni][1] *= a0;
            Of[ni][2] *= a1; Of[ni][3] *= a1;
        }

        uint32_t pf[4][4];
        #pragma unroll
        for (int kk2 = 0; kk2 < 4; kk2++) {
            pf[kk2][0] = packh2(S[2 * kk2][0],     S[2 * kk2][1]);
            pf[kk2][1] = packh2(S[2 * kk2][2],     S[2 * kk2][3]);
            pf[kk2][2] = packh2(S[2 * kk2 + 1][0], S[2 * kk2 + 1][1]);
            pf[kk2][3] = packh2(S[2 * kk2 + 1][2], S[2 * kk2 + 1][3]);
        }

        #pragma unroll
        for (int vp = 0; vp < 8; vp++) {
            #pragma unroll
            for (int kk2 = 0; kk2 < 4; kk2++) {
                uint32_t r0, r1, r2, r3;
                ldm4(r0, r1, r2, r3,
                     vbase + (uint32_t)((vp * 16 + lrow) * VLD + kk2 * 16 + lcol) * 2);
                uint32_t b0[2] = {r0, r2}, b1[2] = {r1, r3};
                mma_f16(Of[2 * vp],     pf[kk2], b0);
                mma_f16(Of[2 * vp + 1], pf[kk2], b1);
            }
        }
    }

    const float i0 = 1.f / l0, i1 = 1.f / l1;
    const int tok0 = b * SEQ + q0 + wid * 16 + gid;
    #pragma unroll
    for (int ni = 0; ni < 16; ni++) {
        const int col = h * HD + ni * 8 + 2 * tig;
        *(__half2*)(attnH + (size_t)tok0 * DMODEL + col) =
            __floats2half2_rn(Of[ni][0] * i0, Of[ni][1] * i0);
        *(__half2*)(attnH + (size_t)(tok0 + 8) * DMODEL + col) =
            __floats2half2_rn(Of[ni][2] * i1, Of[ni][3] * i1);
    }
}

// ---------------------------------------------------------------------------
extern "C" void kernel_launch(void* const* d_in, const int* in_sizes, int n_in,
                              void* d_out, int out_size)
{
    const float* hidden = (const float*)d_in[0];
    const float* cosT   = (const float*)d_in[1];
    const float* sinT   = (const float*)d_in[2];
    const float* Wqkv   = (const float*)d_in[3];
    const float* Wout   = (const float*)d_in[4];
    float* out = (float*)d_out;

    __half *qkvh, *Xh, *WqTh, *WoTh, *Qh, *Kh, *Vt, *attnH;
    cudaGetSymbolAddress((void**)&qkvh,  g_qkvh);
    cudaGetSymbolAddress((void**)&Xh,    g_Xh);
    cudaGetSymbolAddress((void**)&WqTh,  g_WqTh);
    cudaGetSymbolAddress((void**)&WoTh,  g_WoTh);
    cudaGetSymbolAddress((void**)&Qh,    g_Qh);
    cudaGetSymbolAddress((void**)&Kh,    g_Kh);
    cudaGetSymbolAddress((void**)&Vt,    g_Vt);
    cudaGetSymbolAddress((void**)&attnH, g_attnH);

    cudaFuncSetAttribute(gemm_mma_f16<true>,
                         cudaFuncAttributeMaxDynamicSharedMemorySize, GEMM_SMEM);
    cudaFuncSetAttribute(gemm_mma_f16<false>,
                         cudaFuncAttributeMaxDynamicSharedMemorySize, GEMM_SMEM);
    cudaFuncSetAttribute(flash_mma,
                         cudaFuncAttributeMaxDynamicSharedMemorySize, FLASH_SMEM);

    // 0) fp16 conversions
    f32_to_f16_kernel<<<2048, 256>>>((const float4*)hidden, (__half2*)Xh,
                                     MTOK * DMODEL / 4);
    transpose_f16_kernel<<<dim3(QKVD / 32, DMODEL / 32), dim3(32, 8)>>>(
        Wqkv, WqTh, DMODEL, QKVD);
    transpose_f16_kernel<<<dim3(DMODEL / 32, DMODEL / 32), dim3(32, 8)>>>(
        Wout, WoTh, DMODEL, DMODEL);

    // 1) QKV projection (fp16 out), CTA tile 256x128
    gemm_mma_f16<true><<<dim3(QKVD / 128, MTOK / 256), 256, GEMM_SMEM>>>(
        Xh, WqTh, qkvh, QKVD, DMODEL);

    // 2) RoPE + pack; V transpose
    rope_pack_kernel<<<dim3(MTOK, NHEADS + NKV), 64>>>(qkvh, cosT, sinT, Qh, Kh);
    v_pack_kernel<<<dim3(SEQ / 32, HD / 32, BATCH * NKV), dim3(32, 8)>>>(qkvh, Vt);

    // 3) Flash attention
    flash_mma<<<dim3(SEQ / 128, BATCH * NHEADS), 256, FLASH_SMEM>>>(
        Qh, Kh, Vt, attnH);

    // 4) Output projection (fp32 out)
    gemm_mma_f16<false><<<dim3(DMODEL / 128, MTOK / 256), 256, GEMM_SMEM>>>(
        attnH, WoTh, out, DMODEL, DMODEL);
}

// round 10
// speedup vs baseline: 1.0944x; 1.0944x over previous
#include <cuda_runtime.h>
#include <cuda_fp16.h>
#include <math.h>
#include <stdint.h>

#define BATCH   2
#define SEQ     2048
#define DMODEL  4096
#define NHEADS  32
#define NKV     8
#define HD      128
#define QKVD    6144            // (32 + 2*8) * 128
#define MTOK    (BATCH * SEQ)   // 4096

// Scratch (allocation-free rule: __device__ globals)
__device__ __half g_qkvh [(size_t)MTOK * QKVD];
__device__ __half g_Xh   [(size_t)MTOK * DMODEL];
__device__ __half g_WqTh [(size_t)QKVD * DMODEL];
__device__ __half g_WoTh [(size_t)DMODEL * DMODEL];
__device__ __half g_Qh   [(size_t)BATCH * NHEADS * SEQ * HD];
__device__ __half g_Kh   [(size_t)BATCH * NKV * SEQ * HD];
__device__ __half g_Vt   [(size_t)BATCH * NKV * HD * SEQ];
__device__ __half g_attnH[(size_t)MTOK * DMODEL];

// ---------------------------------------------------------------------------
// Helpers (baseline PTX only)
// ---------------------------------------------------------------------------
__device__ __forceinline__ uint32_t s2u(const void* p) {
    uint32_t a;
    asm("{ .reg .u64 t; cvta.to.shared.u64 t, %1; cvt.u32.u64 %0, t; }"
        : "=r"(a) : "l"(p));
    return a;
}
__device__ __forceinline__ void cp_async16(uint32_t dst, const void* src) {
    asm volatile("cp.async.cg.shared.global [%0], [%1], 16;"
                 :: "r"(dst), "l"(src) : "memory");
}
__device__ __forceinline__ void mma_f16(float* c, const uint32_t* a,
                                        const uint32_t* b) {
    asm volatile(
        "mma.sync.aligned.m16n8k16.row.col.f32.f16.f16.f32 "
        "{%0,%1,%2,%3}, {%4,%5,%6,%7}, {%8,%9}, {%0,%1,%2,%3};"
        : "+f"(c[0]), "+f"(c[1]), "+f"(c[2]), "+f"(c[3])
        : "r"(a[0]), "r"(a[1]), "r"(a[2]), "r"(a[3]), "r"(b[0]), "r"(b[1]));
}
__device__ __forceinline__ void ldm4(uint32_t& r0, uint32_t& r1,
                                     uint32_t& r2, uint32_t& r3, uint32_t addr) {
    asm volatile("ldmatrix.sync.aligned.m8n8.x4.shared.b16 {%0,%1,%2,%3}, [%4];"
                 : "=r"(r0), "=r"(r1), "=r"(r2), "=r"(r3) : "r"(addr));
}
__device__ __forceinline__ uint32_t packh2(float x, float y) {
    __half2 h = __floats2half2_rn(x, y);
    return *(uint32_t*)&h;
}

// ---------------------------------------------------------------------------
// Prep kernels
// ---------------------------------------------------------------------------
__global__ void f32_to_f16_kernel(const float4* __restrict__ in,
                                  __half2* __restrict__ out, int n4) {
    for (int i = blockIdx.x * blockDim.x + threadIdx.x; i < n4;
         i += gridDim.x * blockDim.x) {
        float4 v = in[i];
        out[2 * i]     = __floats2half2_rn(v.x, v.y);
        out[2 * i + 1] = __floats2half2_rn(v.z, v.w);
    }
}

__global__ void transpose_f16_kernel(const float* __restrict__ in,
                                     __half* __restrict__ out, int R, int C) {
    __shared__ float t[32][33];
    int cb = blockIdx.x * 32, rb = blockIdx.y * 32;
    int tx = threadIdx.x, ty = threadIdx.y;
    #pragma unroll
    for (int i = 0; i < 4; i++)
        t[ty + i * 8][tx] = in[(size_t)(rb + ty + i * 8) * C + cb + tx];
    __syncthreads();
    #pragma unroll
    for (int i = 0; i < 4; i++)
        out[(size_t)(cb + ty + i * 8) * R + rb + tx] =
            __float2half_rn(t[tx][ty + i * 8]);
}

// ---------------------------------------------------------------------------
// fp16 mma.sync GEMM: C[M,N] = A[M,K] @ Bt[N,K]^T   (fp16, K-major)
// CTA tile 128x128, BK=32, 128 thr = 4 warps (2M x 2N), warp tile 64x64.
// Two CTAs per SM (sync interleaving) + high frag reuse (8 ldm4 : 32 mma).
// 3-stage cp.async pipeline. HALF_OUT selects C dtype.
// ---------------------------------------------------------------------------
#define GLD   40                                  // smem stride in halves
#define GA_B  (128 * GLD * 2)                     // A bytes per stage (10240)
#define GB_B  (128 * GLD * 2)                     // B bytes per stage (10240)
#define GSTG  (GA_B + GB_B)                       // 20480
#define GEMM_SMEM (3 * GSTG)                      // 61440

template<bool HALF_OUT>
__global__ __launch_bounds__(128, 2) void gemm_mma_f16(
    const __half* __restrict__ A, const __half* __restrict__ Bt,
    void* __restrict__ Cv, int N, int K)
{
    extern __shared__ char dsm[];
    const int tid  = threadIdx.x;
    const int wid  = tid >> 5;
    const int lane = tid & 31;
    const int gid  = lane >> 2;
    const int tig  = lane & 3;
    const int wm   = (wid >> 1) * 64;   // 2 M-warp slots
    const int wn   = (wid & 1) * 64;    // 2 N-warp slots
    const int m0 = blockIdx.y * 128;
    const int n0 = blockIdx.x * 128;
    const uint32_t sb = s2u(dsm);

    const int lrow = ((lane >> 3) & 1) * 8 + (lane & 7);
    const int lcol = (lane >> 4) * 8;

    const __half* Ab = A  + (size_t)m0 * K;
    const __half* Bb = Bt + (size_t)n0 * K;
    const int NC = K >> 5;

    // A tile 128x32 halves = 512 x 16B; B same. 1024 cp.async / 128 thr = 8.
    #define GLOAD(kc, st)                                                      \
    {                                                                          \
        uint32_t sbase = sb + (st) * GSTG;                                     \
        _Pragma("unroll")                                                      \
        for (int i = 0; i < 4; i++) {                                          \
            int idx = i * 128 + tid;                                           \
            int r = idx >> 2, c8 = idx & 3;                                    \
            cp_async16(sbase + (uint32_t)(r * GLD + c8 * 8) * 2,               \
                       Ab + (size_t)r * K + (kc) * 32 + c8 * 8);               \
        }                                                                      \
        _Pragma("unroll")                                                      \
        for (int i = 0; i < 4; i++) {                                          \
            int idx = i * 128 + tid;                                           \
            int r = idx >> 2, c8 = idx & 3;                                    \
            cp_async16(sbase + GA_B + (uint32_t)(r * GLD + c8 * 8) * 2,        \
                       Bb + (size_t)r * K + (kc) * 32 + c8 * 8);               \
        }                                                                      \
        asm volatile("cp.async.commit_group;" ::: "memory");                   \
    }

    float acc[4][8][4];
    #pragma unroll
    for (int mi = 0; mi < 4; mi++)
        #pragma unroll
        for (int ni = 0; ni < 8; ni++)
            #pragma unroll
            for (int q = 0; q < 4; q++) acc[mi][ni][q] = 0.f;

    GLOAD(0, 0);
    GLOAD(1, 1);

    for (int kc = 0; kc < NC; kc++) {
        if (kc + 1 < NC) asm volatile("cp.async.wait_group 1;" ::: "memory");
        else             asm volatile("cp.async.wait_group 0;" ::: "memory");
        __syncthreads();
        if (kc + 2 < NC) GLOAD(kc + 2, (kc + 2) % 3);

        const uint32_t sA = sb + (kc % 3) * GSTG;
        const uint32_t sB = sA + GA_B;

        #pragma unroll
        for (int ks = 0; ks < 2; ks++) {
            const int k0h = ks * 16;
            uint32_t af[4][4], bf[8][2];
            #pragma unroll
            for (int mi = 0; mi < 4; mi++)
                ldm4(af[mi][0], af[mi][1], af[mi][2], af[mi][3],
                     sA + (uint32_t)((wm + mi * 16 + lrow) * GLD + k0h + lcol) * 2);
            #pragma unroll
            for (int np = 0; np < 4; np++) {
                uint32_t r0, r1, r2, r3;
                ldm4(r0, r1, r2, r3,
                     sB + (uint32_t)((wn + np * 16 + lrow) * GLD + k0h + lcol) * 2);
                bf[2 * np][0] = r0;     bf[2 * np][1] = r2;
                bf[2 * np + 1][0] = r1; bf[2 * np + 1][1] = r3;
            }
            #pragma unroll
            for (int mi = 0; mi < 4; mi++)
                #pragma unroll
                for (int ni = 0; ni < 8; ni++)
                    mma_f16(acc[mi][ni], af[mi], bf[ni]);
        }
    }

    #pragma unroll
    for (int mi = 0; mi < 4; mi++) {
        const int r0 = m0 + wm + mi * 16 + gid;
        #pragma unroll
        for (int ni = 0; ni < 8; ni++) {
            const int c = n0 + wn + ni * 8 + 2 * tig;
            if (HALF_OUT) {
                __half* C = (__half*)Cv;
                *(__half2*)(C + (size_t)r0 * N + c) =
                    __floats2half2_rn(acc[mi][ni][0], acc[mi][ni][1]);
                *(__half2*)(C + (size_t)(r0 + 8) * N + c) =
                    __floats2half2_rn(acc[mi][ni][2], acc[mi][ni][3]);
            } else {
                float* C = (float*)Cv;
                *(float2*)(C + (size_t)r0 * N + c) =
                    make_float2(acc[mi][ni][0], acc[mi][ni][1]);
                *(float2*)(C + (size_t)(r0 + 8) * N + c) =
                    make_float2(acc[mi][ni][2], acc[mi][ni][3]);
            }
        }
    }
}

// ---------------------------------------------------------------------------
// RoPE + pack: fp16 qkv -> fp16 Qh [b][h][s][d], Kh [b][kv][s][d]
// ---------------------------------------------------------------------------
__global__ void rope_pack_kernel(const __half* __restrict__ qkv,
                                 const float* __restrict__ cosT,
                                 const float* __restrict__ sinT,
                                 __half* __restrict__ Qh,
                                 __half* __restrict__ Kh)
{
    const int token = blockIdx.x;
    const int head  = blockIdx.y;   // 0..39
    const int b = token >> 11;
    const int s = token & (SEQ - 1);
    const int d = threadIdx.x;      // 0..63

    const __half* p = qkv + (size_t)token * QKVD + head * HD;
    const float c  = cosT[s * HD + d];
    const float sn = sinT[s * HD + d];
    const float x1 = __half2float(p[d]);
    const float x2 = __half2float(p[d + 64]);
    const float o1 = x1 * c - x2 * sn;
    const float o2 = x2 * c + x1 * sn;

    __half* dst = (head < NHEADS)
        ? Qh + ((size_t)(b * NHEADS + head) * SEQ + s) * HD
        : Kh + ((size_t)(b * NKV + head - NHEADS) * SEQ + s) * HD;
    dst[d]      = __float2half_rn(o1);
    dst[d + 64] = __float2half_rn(o2);
}

// V pack: fp16 qkv V region -> fp16 transposed Vt [b][kv][d][s]
__global__ void v_pack_kernel(const __half* __restrict__ qkv,
                              __half* __restrict__ Vt)
{
    __shared__ __half t[32][34];
    const int sx = blockIdx.x * 32;
    const int dy = blockIdx.y * 32;
    const int bkv = blockIdx.z;
    const int b = bkv >> 3, kvh = bkv & 7;
    const int tx = threadIdx.x, ty = threadIdx.y;

    #pragma unroll
    for (int i = 0; i < 4; i++)
        t[ty + i * 8][tx] = qkv[(size_t)(b * SEQ + sx + ty + i * 8) * QKVD +
                                (NHEADS + NKV) * HD + kvh * HD + dy + tx];
    __syncthreads();
    #pragma unroll
    for (int i = 0; i < 4; i++)
        Vt[((size_t)(b * NKV + kvh) * HD + dy + ty + i * 8) * SEQ + sx + tx] =
            t[tx][ty + i * 8];
}

// ---------------------------------------------------------------------------
// Flash attention, mma.sync fp16, ldmatrix fragment fetch.
// BQ=128, BK=64, 256 thr = 8 warps, warp owns 16 q rows. (round-7 version)
// ---------------------------------------------------------------------------
#define QLD 136
#define KLD 136
#define VLD 72
#define K_TILE_B (64 * KLD * 2)
#define V_TILE_B (128 * VLD * 2)
#define STAGE_B  (K_TILE_B + V_TILE_B)
#define FLASH_SMEM (2 * STAGE_B)

__global__ __launch_bounds__(256) void flash_mma(
    const __half* __restrict__ Qh, const __half* __restrict__ Kh,
    const __half* __restrict__ Vt, __half* __restrict__ attnH)
{
    extern __shared__ char dsm[];
    const int tid = threadIdx.x;
    const int wid = tid >> 5, lane = tid & 31;
    const int gid = lane >> 2, tig = lane & 3;
    const int lrow = ((lane >> 3) & 1) * 8 + (lane & 7);
    const int lcol = (lane >> 4) * 8;
    const int qt = (gridDim.x - 1) - blockIdx.x;
    const int bh = blockIdx.y;
    const int b = bh >> 5, h = bh & 31, kvh = h >> 2;
    const int q0 = qt * 128;
    const uint32_t sb = s2u(dsm);
    const float scale = 0.08838834764831845f;

    const __half* Qg = Qh + ((size_t)(b * NHEADS + h) * SEQ + q0) * HD;
    const __half* Kg = Kh + (size_t)(b * NKV + kvh) * SEQ * HD;
    const __half* Vg = Vt + (size_t)(b * NKV + kvh) * HD * SEQ;

    #pragma unroll
    for (int i = 0; i < 8; i++) {
        int idx = i * 256 + tid;
        int r = idx >> 4, c = idx & 15;
        cp_async16(sb + (uint32_t)(r * QLD + c * 8) * 2,
                   Qg + (size_t)r * HD + c * 8);
    }
    asm volatile("cp.async.commit_group;" ::: "memory");
    asm volatile("cp.async.wait_group 0;" ::: "memory");
    __syncthreads();

    uint32_t qf[8][4];
    #pragma unroll
    for (int kk = 0; kk < 8; kk++)
        ldm4(qf[kk][0], qf[kk][1], qf[kk][2], qf[kk][3],
             sb + (uint32_t)((wid * 16 + lrow) * QLD + kk * 16 + lcol) * 2);
    __syncthreads();

    #define LOADKV(kt, st)                                                     \
    {                                                                          \
        const int k0_ = (kt) * 64;                                             \
        uint32_t base_ = sb + (st) * STAGE_B;                                  \
        _Pragma("unroll")                                                      \
        for (int i_ = 0; i_ < 4; i_++) {                                       \
            int idx_ = i_ * 256 + tid;                                         \
            int r_ = idx_ >> 4, c_ = idx_ & 15;                                \
            cp_async16(base_ + (uint32_t)(r_ * KLD + c_ * 8) * 2,              \
                       Kg + (size_t)(k0_ + r_) * HD + c_ * 8);                 \
        }                                                                      \
        _Pragma("unroll")                                                      \
        for (int i_ = 0; i_ < 4; i_++) {                                       \
            int idx_ = i_ * 256 + tid;                                         \
            int d_ = idx_ >> 3, c_ = idx_ & 7;                                 \
            cp_async16(base_ + K_TILE_B + (uint32_t)(d_ * VLD + c_ * 8) * 2,   \
                       Vg + (size_t)d_ * SEQ + k0_ + c_ * 8);                  \
        }                                                                      \
        asm volatile("cp.async.commit_group;" ::: "memory");                   \
    }

    float Of[16][4];
    #pragma unroll
    for (int ni = 0; ni < 16; ni++)
        #pragma unroll
        for (int q = 0; q < 4; q++) Of[ni][q] = 0.f;
    float m0 = -INFINITY, m1 = -INFINITY, l0 = 0.f, l1 = 0.f;
    const int nkt = 2 * qt + 2;

    LOADKV(0, 0);

    for (int kt = 0; kt < nkt; kt++) {
        const int s = kt & 1;
        asm volatile("cp.async.wait_group 0;" ::: "memory");
        __syncthreads();
        if (kt + 1 < nkt) LOADKV(kt + 1, s ^ 1);

        const uint32_t kbase = sb + s * STAGE_B;
        const uint32_t vbase = kbase + K_TILE_B;
        const int k0 = kt * 64;

        float S[8][4];
        #pragma unroll
        for (int ni = 0; ni < 8; ni++)
            S[ni][0] = S[ni][1] = S[ni][2] = S[ni][3] = 0.f;
        #pragma unroll
        for (int np = 0; np < 4; np++) {
            #pragma unroll
            for (int kk = 0; kk < 8; kk++) {
                uint32_t r0, r1, r2, r3;
                ldm4(r0, r1, r2, r3,
                     kbase + (uint32_t)((np * 16 + lrow) * KLD + kk * 16 + lcol) * 2);
                uint32_t b0[2] = {r0, r2}, b1[2] = {r1, r3};
                mma_f16(S[2 * np],     qf[kk], b0);
                mma_f16(S[2 * np + 1], qf[kk], b1);
            }
        }

        const int row0 = q0 + wid * 16 + gid, row1 = row0 + 8;
        #pragma unroll
        for (int ni = 0; ni < 8; ni++) {
            const int col = k0 + ni * 8 + 2 * tig;
            S[ni][0] = (col     <= row0) ? S[ni][0] * scale : -1e30f;
            S[ni][1] = (col + 1 <= row0) ? S[ni][1] * scale : -1e30f;
            S[ni][2] = (col     <= row1) ? S[ni][2] * scale : -1e30f;
            S[ni][3] = (col + 1 <= row1) ? S[ni][3] * scale : -1e30f;
        }

        float mx0 = fmaxf(S[0][0], S[0][1]), mx1 = fmaxf(S[0][2], S[0][3]);
        #pragma unroll
        for (int ni = 1; ni < 8; ni++) {
            mx0 = fmaxf(mx0, fmaxf(S[ni][0], S[ni][1]));
            mx1 = fmaxf(mx1, fmaxf(S[ni][2], S[ni][3]));
        }
        mx0 = fmaxf(mx0, __shfl_xor_sync(0xFFFFFFFFu, mx0, 1));
        mx0 = fmaxf(mx0, __shfl_xor_sync(0xFFFFFFFFu, mx0, 2));
        mx1 = fmaxf(mx1, __shfl_xor_sync(0xFFFFFFFFu, mx1, 1));
        mx1 = fmaxf(mx1, __shfl_xor_sync(0xFFFFFFFFu, mx1, 2));
        const float mn0 = fmaxf(m0, mx0), mn1 = fmaxf(m1, mx1);
        const float a0 = __expf(m0 - mn0), a1 = __expf(m1 - mn1);
        float s0 = 0.f, s1 = 0.f;
        #pragma unroll
        for (int ni = 0; ni < 8; ni++) {
            S[ni][0] = __expf(S[ni][0] - mn0);
            S[ni][1] = __expf(S[ni][1] - mn0);
            S[ni][2] = __expf(S[ni][2] - mn1);
            S[ni][3] = __expf(S[ni][3] - mn1);
            s0 += S[ni][0] + S[ni][1];
            s1 += S[ni][2] + S[ni][3];
        }
        s0 += __shfl_xor_sync(0xFFFFFFFFu, s0, 1);
        s0 += __shfl_xor_sync(0xFFFFFFFFu, s0, 2);
        s1 += __shfl_xor_sync(0xFFFFFFFFu, s1, 1);
        s1 += __shfl_xor_sync(0xFFFFFFFFu, s1, 2);
        l0 = l0 * a0 + s0;  l1 = l1 * a1 + s1;
        m0 = mn0;  m1 = mn1;

        #pragma unroll
        for (int ni = 0; ni < 16; ni++) {
            Of[ni][0] *= a0; Of[ni][1] *= a0;
            Of[ni][2] *= a1; Of[ni][3] *= a1;
        }

        uint32_t pf[4][4];
        #pragma unroll
        for (int kk2 = 0; kk2 < 4; kk2++) {
            pf[kk2][0] = packh2(S[2 * kk2][0],     S[2 * kk2][1]);
            pf[kk2][1] = packh2(S[2 * kk2][2],     S[2 * kk2][3]);
            pf[kk2][2] = packh2(S[2 * kk2 + 1][0], S[2 * kk2 + 1][1]);
            pf[kk2][3] = packh2(S[2 * kk2 + 1][2], S[2 * kk2 + 1][3]);
        }

        #pragma unroll
        for (int vp = 0; vp < 8; vp++) {
            #pragma unroll
            for (int kk2 = 0; kk2 < 4; kk2++) {
                uint32_t r0, r1, r2, r3;
                ldm4(r0, r1, r2, r3,
                     vbase + (uint32_t)((vp * 16 + lrow) * VLD + kk2 * 16 + lcol) * 2);
                uint32_t b0[2] = {r0, r2}, b1[2] = {r1, r3};
                mma_f16(Of[2 * vp],     pf[kk2], b0);
                mma_f16(Of[2 * vp + 1], pf[kk2], b1);
            }
        }
    }

    const float i0 = 1.f / l0, i1 = 1.f / l1;
    const int tok0 = b * SEQ + q0 + wid * 16 + gid;
    #pragma unroll
    for (int ni = 0; ni < 16; ni++) {
        const int col = h * HD + ni * 8 + 2 * tig;
        *(__half2*)(attnH + (size_t)tok0 * DMODEL + col) =
            __floats2half2_rn(Of[ni][0] * i0, Of[ni][1] * i0);
        *(__half2*)(attnH + (size_t)(tok0 + 8) * DMODEL + col) =
            __floats2half2_rn(Of[ni][2] * i1, Of[ni][3] * i1);
    }
}

// ---------------------------------------------------------------------------
extern "C" void kernel_launch(void* const* d_in, const int* in_sizes, int n_in,
                              void* d_out, int out_size)
{
    const float* hidden = (const float*)d_in[0];
    const float* cosT   = (const float*)d_in[1];
    const float* sinT   = (const float*)d_in[2];
    const float* Wqkv   = (const float*)d_in[3];
    const float* Wout   = (const float*)d_in[4];
    float* out = (float*)d_out;

    __half *qkvh, *Xh, *WqTh, *WoTh, *Qh, *Kh, *Vt, *attnH;
    cudaGetSymbolAddress((void**)&qkvh,  g_qkvh);
    cudaGetSymbolAddress((void**)&Xh,    g_Xh);
    cudaGetSymbolAddress((void**)&WqTh,  g_WqTh);
    cudaGetSymbolAddress((void**)&WoTh,  g_WoTh);
    cudaGetSymbolAddress((void**)&Qh,    g_Qh);
    cudaGetSymbolAddress((void**)&Kh,    g_Kh);
    cudaGetSymbolAddress((void**)&Vt,    g_Vt);
    cudaGetSymbolAddress((void**)&attnH, g_attnH);

    cudaFuncSetAttribute(gemm_mma_f16<true>,
                         cudaFuncAttributeMaxDynamicSharedMemorySize, GEMM_SMEM);
    cudaFuncSetAttribute(gemm_mma_f16<false>,
                         cudaFuncAttributeMaxDynamicSharedMemorySize, GEMM_SMEM);
    cudaFuncSetAttribute(flash_mma,
                         cudaFuncAttributeMaxDynamicSharedMemorySize, FLASH_SMEM);

    // 0) fp16 conversions
    f32_to_f16_kernel<<<2048, 256>>>((const float4*)hidden, (__half2*)Xh,
                                     MTOK * DMODEL / 4);
    transpose_f16_kernel<<<dim3(QKVD / 32, DMODEL / 32), dim3(32, 8)>>>(
        Wqkv, WqTh, DMODEL, QKVD);
    transpose_f16_kernel<<<dim3(DMODEL / 32, DMODEL / 32), dim3(32, 8)>>>(
        Wout, WoTh, DMODEL, DMODEL);

    // 1) QKV projection (fp16 out), CTA 128x128, 4 warps, 2 CTAs/SM
    gemm_mma_f16<true><<<dim3(QKVD / 128, MTOK / 128), 128, GEMM_SMEM>>>(
        Xh, WqTh, qkvh, QKVD, DMODEL);

    // 2) RoPE + pack; V transpose
    rope_pack_kernel<<<dim3(MTOK, NHEADS + NKV), 64>>>(qkvh, cosT, sinT, Qh, Kh);
    v_pack_kernel<<<dim3(SEQ / 32, HD / 32, BATCH * NKV), dim3(32, 8)>>>(qkvh, Vt);

    // 3) Flash attention
    flash_mma<<<dim3(SEQ / 128, BATCH * NHEADS), 256, FLASH_SMEM>>>(
        Qh, Kh, Vt, attnH);

    // 4) Output projection (fp32 out)
    gemm_mma_f16<false><<<dim3(DMODEL / 128, MTOK / 128), 128, GEMM_SMEM>>>(
        attnH, WoTh, out, DMODEL, DMODEL);
}

// round 12
// speedup vs baseline: 1.1572x; 1.0573x over previous
#include <cuda_runtime.h>
#include <cuda_fp16.h>
#include <math.h>
#include <stdint.h>

#define BATCH   2
#define SEQ     2048
#define DMODEL  4096
#define NHEADS  32
#define NKV     8
#define HD      128
#define QKVD    6144            // (32 + 2*8) * 128
#define MTOK    (BATCH * SEQ)   // 4096

// Scratch (allocation-free rule: __device__ globals)
__device__ __half g_qkvh [(size_t)MTOK * QKVD];
__device__ __half g_Xh   [(size_t)MTOK * DMODEL];
__device__ __half g_WqTh [(size_t)QKVD * DMODEL];
__device__ __half g_WoTh [(size_t)DMODEL * DMODEL];
__device__ __half g_attnH[(size_t)MTOK * DMODEL];

// ---------------------------------------------------------------------------
// Helpers (baseline PTX only)
// ---------------------------------------------------------------------------
__device__ __forceinline__ uint32_t s2u(const void* p) {
    uint32_t a;
    asm("{ .reg .u64 t; cvta.to.shared.u64 t, %1; cvt.u32.u64 %0, t; }"
        : "=r"(a) : "l"(p));
    return a;
}
__device__ __forceinline__ void cp_async16(uint32_t dst, const void* src) {
    asm volatile("cp.async.cg.shared.global [%0], [%1], 16;"
                 :: "r"(dst), "l"(src) : "memory");
}
__device__ __forceinline__ void mma_f16(float* c, const uint32_t* a,
                                        const uint32_t* b) {
    asm volatile(
        "mma.sync.aligned.m16n8k16.row.col.f32.f16.f16.f32 "
        "{%0,%1,%2,%3}, {%4,%5,%6,%7}, {%8,%9}, {%0,%1,%2,%3};"
        : "+f"(c[0]), "+f"(c[1]), "+f"(c[2]), "+f"(c[3])
        : "r"(a[0]), "r"(a[1]), "r"(a[2]), "r"(a[3]), "r"(b[0]), "r"(b[1]));
}
__device__ __forceinline__ void ldm4(uint32_t& r0, uint32_t& r1,
                                     uint32_t& r2, uint32_t& r3, uint32_t addr) {
    asm volatile("ldmatrix.sync.aligned.m8n8.x4.shared.b16 {%0,%1,%2,%3}, [%4];"
                 : "=r"(r0), "=r"(r1), "=r"(r2), "=r"(r3) : "r"(addr));
}
__device__ __forceinline__ void ldm4t(uint32_t& r0, uint32_t& r1,
                                      uint32_t& r2, uint32_t& r3, uint32_t addr) {
    asm volatile("ldmatrix.sync.aligned.m8n8.x4.trans.shared.b16 {%0,%1,%2,%3}, [%4];"
                 : "=r"(r0), "=r"(r1), "=r"(r2), "=r"(r3) : "r"(addr));
}
__device__ __forceinline__ uint32_t packh2(float x, float y) {
    __half2 h = __floats2half2_rn(x, y);
    return *(uint32_t*)&h;
}

// ---------------------------------------------------------------------------
// Prep kernels
// ---------------------------------------------------------------------------
__global__ void f32_to_f16_kernel(const float4* __restrict__ in,
                                  __half2* __restrict__ out, int n4) {
    for (int i = blockIdx.x * blockDim.x + threadIdx.x; i < n4;
         i += gridDim.x * blockDim.x) {
        float4 v = in[i];
        out[2 * i]     = __floats2half2_rn(v.x, v.y);
        out[2 * i + 1] = __floats2half2_rn(v.z, v.w);
    }
}

__global__ void transpose_f16_kernel(const float* __restrict__ in,
                                     __half* __restrict__ out, int R, int C) {
    __shared__ float t[32][33];
    int cb = blockIdx.x * 32, rb = blockIdx.y * 32;
    int tx = threadIdx.x, ty = threadIdx.y;
    #pragma unroll
    for (int i = 0; i < 4; i++)
        t[ty + i * 8][tx] = in[(size_t)(rb + ty + i * 8) * C + cb + tx];
    __syncthreads();
    #pragma unroll
    for (int i = 0; i < 4; i++)
        out[(size_t)(cb + ty + i * 8) * R + rb + tx] =
            __float2half_rn(t[tx][ty + i * 8]);
}

// ---------------------------------------------------------------------------
// fp16 mma.sync GEMM: C[M,N] = A[M,K] @ Bt[N,K]^T   (fp16, K-major)
// CTA tile 128x128, BK=32, 128 thr = 4 warps (2M x 2N), warp tile 64x64.
// Two CTAs per SM + high frag reuse. 3-stage cp.async pipeline.
// (At the legacy-HMMA dispatch floor of ~1 HMMA/cyc/SM — do not touch.)
// ---------------------------------------------------------------------------
#define GLD   40
#define GA_B  (128 * GLD * 2)
#define GB_B  (128 * GLD * 2)
#define GSTG  (GA_B + GB_B)
#define GEMM_SMEM (3 * GSTG)

template<bool HALF_OUT>
__global__ __launch_bounds__(128, 2) void gemm_mma_f16(
    const __half* __restrict__ A, const __half* __restrict__ Bt,
    void* __restrict__ Cv, int N, int K)
{
    extern __shared__ char dsm[];
    const int tid  = threadIdx.x;
    const int wid  = tid >> 5;
    const int lane = tid & 31;
    const int gid  = lane >> 2;
    const int tig  = lane & 3;
    const int wm   = (wid >> 1) * 64;
    const int wn   = (wid & 1) * 64;
    const int m0 = blockIdx.y * 128;
    const int n0 = blockIdx.x * 128;
    const uint32_t sb = s2u(dsm);

    const int lrow = ((lane >> 3) & 1) * 8 + (lane & 7);
    const int lcol = (lane >> 4) * 8;

    const __half* Ab = A  + (size_t)m0 * K;
    const __half* Bb = Bt + (size_t)n0 * K;
    const int NC = K >> 5;

    #define GLOAD(kc, st)                                                      \
    {                                                                          \
        uint32_t sbase = sb + (st) * GSTG;                                     \
        _Pragma("unroll")                                                      \
        for (int i = 0; i < 4; i++) {                                          \
            int idx = i * 128 + tid;                                           \
            int r = idx >> 2, c8 = idx & 3;                                    \
            cp_async16(sbase + (uint32_t)(r * GLD + c8 * 8) * 2,               \
                       Ab + (size_t)r * K + (kc) * 32 + c8 * 8);               \
        }                                                                      \
        _Pragma("unroll")                                                      \
        for (int i = 0; i < 4; i++) {                                          \
            int idx = i * 128 + tid;                                           \
            int r = idx >> 2, c8 = idx & 3;                                    \
            cp_async16(sbase + GA_B + (uint32_t)(r * GLD + c8 * 8) * 2,        \
                       Bb + (size_t)r * K + (kc) * 32 + c8 * 8);               \
        }                                                                      \
        asm volatile("cp.async.commit_group;" ::: "memory");                   \
    }

    float acc[4][8][4];
    #pragma unroll
    for (int mi = 0; mi < 4; mi++)
        #pragma unroll
        for (int ni = 0; ni < 8; ni++)
            #pragma unroll
            for (int q = 0; q < 4; q++) acc[mi][ni][q] = 0.f;

    GLOAD(0, 0);
    GLOAD(1, 1);

    for (int kc = 0; kc < NC; kc++) {
        if (kc + 1 < NC) asm volatile("cp.async.wait_group 1;" ::: "memory");
        else             asm volatile("cp.async.wait_group 0;" ::: "memory");
        __syncthreads();
        if (kc + 2 < NC) GLOAD(kc + 2, (kc + 2) % 3);

        const uint32_t sA = sb + (kc % 3) * GSTG;
        const uint32_t sB = sA + GA_B;

        #pragma unroll
        for (int ks = 0; ks < 2; ks++) {
            const int k0h = ks * 16;
            uint32_t af[4][4], bf[8][2];
            #pragma unroll
            for (int mi = 0; mi < 4; mi++)
                ldm4(af[mi][0], af[mi][1], af[mi][2], af[mi][3],
                     sA + (uint32_t)((wm + mi * 16 + lrow) * GLD + k0h + lcol) * 2);
            #pragma unroll
            for (int np = 0; np < 4; np++) {
                uint32_t r0, r1, r2, r3;
                ldm4(r0, r1, r2, r3,
                     sB + (uint32_t)((wn + np * 16 + lrow) * GLD + k0h + lcol) * 2);
                bf[2 * np][0] = r0;     bf[2 * np][1] = r2;
                bf[2 * np + 1][0] = r1; bf[2 * np + 1][1] = r3;
            }
            #pragma unroll
            for (int mi = 0; mi < 4; mi++)
                #pragma unroll
                for (int ni = 0; ni < 8; ni++)
                    mma_f16(acc[mi][ni], af[mi], bf[ni]);
        }
    }

    #pragma unroll
    for (int mi = 0; mi < 4; mi++) {
        const int r0 = m0 + wm + mi * 16 + gid;
        #pragma unroll
        for (int ni = 0; ni < 8; ni++) {
            const int c = n0 + wn + ni * 8 + 2 * tig;
            if (HALF_OUT) {
                __half* C = (__half*)Cv;
                *(__half2*)(C + (size_t)r0 * N + c) =
                    __floats2half2_rn(acc[mi][ni][0], acc[mi][ni][1]);
                *(__half2*)(C + (size_t)(r0 + 8) * N + c) =
                    __floats2half2_rn(acc[mi][ni][2], acc[mi][ni][3]);
            } else {
                float* C = (float*)Cv;
                *(float2*)(C + (size_t)r0 * N + c) =
                    make_float2(acc[mi][ni][0], acc[mi][ni][1]);
                *(float2*)(C + (size_t)(r0 + 8) * N + c) =
                    make_float2(acc[mi][ni][2], acc[mi][ni][3]);
            }
        }
    }
}

// ---------------------------------------------------------------------------
// RoPE in-place on qkvh (Q heads 0..31, K heads 32..39), half2-vectorized.
// grid (MTOK, 5), block 256: 8 heads per block, 32 lanes per head.
// ---------------------------------------------------------------------------
__global__ void rope_inplace_kernel(__half* __restrict__ qkv,
                                    const float* __restrict__ cosT,
                                    const float* __restrict__ sinT)
{
    const int token = blockIdx.x;
    const int head  = blockIdx.y * 8 + (threadIdx.x >> 5);  // 0..39
    const int d2    = (threadIdx.x & 31) * 2;               // 0..62
    const int s = token & (SEQ - 1);

    __half* p = qkv + (size_t)token * QKVD + head * HD;
    const float2 c  = *(const float2*)(cosT + s * HD + d2);
    const float2 sn = *(const float2*)(sinT + s * HD + d2);
    const __half2 x1h = *(__half2*)(p + d2);
    const __half2 x2h = *(__half2*)(p + d2 + 64);
    const float x1a = __low2float(x1h), x1b = __high2float(x1h);
    const float x2a = __low2float(x2h), x2b = __high2float(x2h);
    *(__half2*)(p + d2) =
        __floats2half2_rn(x1a * c.x - x2a * sn.x, x1b * c.y - x2b * sn.y);
    *(__half2*)(p + d2 + 64) =
        __floats2half2_rn(x2a * c.x + x1a * sn.x, x2b * c.y + x1b * sn.y);
}

// ---------------------------------------------------------------------------
// Flash attention, mma.sync fp16, ldmatrix fragment fetch.
// Reads Q/K/V directly from qkvh (row stride QKVD). V transposed in the
// ldmatrix unit (.trans) -- no global V repack. BQ=128, BK=64, 8 warps.
// ---------------------------------------------------------------------------
#define QLD 136
#define KLD 136
#define VLD 136
#define K_TILE_B (64 * KLD * 2)     // 17408
#define V_TILE_B (64 * VLD * 2)     // 17408 (64 k-rows x 128 d-cols)
#define STAGE_B  (K_TILE_B + V_TILE_B)
#define FLASH_SMEM (2 * STAGE_B)

__global__ __launch_bounds__(256) void flash_mma(
    const __half* __restrict__ qkv, __half* __restrict__ attnH)
{
    extern __shared__ char dsm[];
    const int tid = threadIdx.x;
    const int wid = tid >> 5, lane = tid & 31;
    const int gid = lane >> 2, tig = lane & 3;
    const int lrow = ((lane >> 3) & 1) * 8 + (lane & 7);
    const int lcol = (lane >> 4) * 8;
    const int qt = (gridDim.x - 1) - blockIdx.x;
    const int bh = blockIdx.y;
    const int b = bh >> 5, h = bh & 31, kvh = h >> 2;
    const int q0 = qt * 128;
    const uint32_t sb = s2u(dsm);
    const float scale = 0.08838834764831845f;

    const __half* Qg = qkv + ((size_t)(b * SEQ + q0)) * QKVD + h * HD;
    const __half* Kg = qkv + (size_t)(b * SEQ) * QKVD + (NHEADS + kvh) * HD;
    const __half* Vg = qkv + (size_t)(b * SEQ) * QKVD + (NHEADS + NKV + kvh) * HD;

    // Stage Q tile (strided rows from qkvh), extract frags via ldmatrix.
    #pragma unroll
    for (int i = 0; i < 8; i++) {
        int idx = i * 256 + tid;
        int r = idx >> 4, c = idx & 15;
        cp_async16(sb + (uint32_t)(r * QLD + c * 8) * 2,
                   Qg + (size_t)r * QKVD + c * 8);
    }
    asm volatile("cp.async.commit_group;" ::: "memory");
    asm volatile("cp.async.wait_group 0;" ::: "memory");
    __syncthreads();

    uint32_t qf[8][4];
    #pragma unroll
    for (int kk = 0; kk < 8; kk++)
        ldm4(qf[kk][0], qf[kk][1], qf[kk][2], qf[kk][3],
             sb + (uint32_t)((wid * 16 + lrow) * QLD + kk * 16 + lcol) * 2);
    __syncthreads();

    // K tile: 64 rows x 128 halves; V tile: 64 k-rows x 128 d-cols (natural).
    #define LOADKV(kt, st)                                                     \
    {                                                                          \
        const int k0_ = (kt) * 64;                                             \
        uint32_t base_ = sb + (st) * STAGE_B;                                  \
        _Pragma("unroll")                                                      \
        for (int i_ = 0; i_ < 2; i_++) {                                       \
            int idx_ = i_ * 256 + tid;                                         \
            int r_ = idx_ >> 3, c_ = idx_ & 7;                                 \
            cp_async16(base_ + (uint32_t)(r_ * KLD + c_ * 16) * 2,             \
                       Kg + (size_t)(k0_ + r_) * QKVD + c_ * 16);              \
            cp_async16(base_ + (uint32_t)(r_ * KLD + c_ * 16 + 8) * 2,        \
                       Kg + (size_t)(k0_ + r_) * QKVD + c_ * 16 + 8);          \
        }                                                                      \
        _Pragma("unroll")                                                      \
        for (int i_ = 0; i_ < 2; i_++) {                                       \
            int idx_ = i_ * 256 + tid;                                         \
            int r_ = idx_ >> 3, c_ = idx_ & 7;                                 \
            cp_async16(base_ + K_TILE_B + (uint32_t)(r_ * VLD + c_ * 16) * 2,  \
                       Vg + (size_t)(k0_ + r_) * QKVD + c_ * 16);              \
            cp_async16(base_ + K_TILE_B + (uint32_t)(r_ * VLD + c_ * 16 + 8) * 2, \
                       Vg + (size_t)(k0_ + r_) * QKVD + c_ * 16 + 8);          \
        }                                                                      \
        asm volatile("cp.async.commit_group;" ::: "memory");                   \
    }

    float Of[16][4];
    #pragma unroll
    for (int ni = 0; ni < 16; ni++)
        #pragma unroll
        for (int q = 0; q < 4; q++) Of[ni][q] = 0.f;
    float m0 = -INFINITY, m1 = -INFINITY, l0 = 0.f, l1 = 0.f;
    const int nkt = 2 * qt + 2;

    LOADKV(0, 0);

    // trans-ldmatrix lane addressing for V (k-row, n-col natural tile):
    const int vkrow = ((lane >> 3) & 1) * 8 + (lane & 7);  // k within 16-chunk
    const int vncol = (lane >> 4) * 8;                     // n within 16-chunk

    for (int kt = 0; kt < nkt; kt++) {
        const int s = kt & 1;
        asm volatile("cp.async.wait_group 0;" ::: "memory");
        __syncthreads();
        if (kt + 1 < nkt) LOADKV(kt + 1, s ^ 1);

        const uint32_t kbase = sb + s * STAGE_B;
        const uint32_t vbase = kbase + K_TILE_B;
        const int k0 = kt * 64;

        float S[8][4];
        #pragma unroll
        for (int ni = 0; ni < 8; ni++)
            S[ni][0] = S[ni][1] = S[ni][2] = S[ni][3] = 0.f;
        #pragma unroll
        for (int np = 0; np < 4; np++) {
            #pragma unroll
            for (int kk = 0; kk < 8; kk++) {
                uint32_t r0, r1, r2, r3;
                ldm4(r0, r1, r2, r3,
                     kbase + (uint32_t)((np * 16 + lrow) * KLD + kk * 16 + lcol) * 2);
                uint32_t b0[2] = {r0, r2}, b1[2] = {r1, r3};
                mma_f16(S[2 * np],     qf[kk], b0);
                mma_f16(S[2 * np + 1], qf[kk], b1);
            }
        }

        const int row0 = q0 + wid * 16 + gid, row1 = row0 + 8;
        #pragma unroll
        for (int ni = 0; ni < 8; ni++) {
            const int col = k0 + ni * 8 + 2 * tig;
            S[ni][0] = (col     <= row0) ? S[ni][0] * scale : -1e30f;
            S[ni][1] = (col + 1 <= row0) ? S[ni][1] * scale : -1e30f;
            S[ni][2] = (col     <= row1) ? S[ni][2] * scale : -1e30f;
            S[ni][3] = (col + 1 <= row1) ? S[ni][3] * scale : -1e30f;
        }

        float mx0 = fmaxf(S[0][0], S[0][1]), mx1 = fmaxf(S[0][2], S[0][3]);
        #pragma unroll
        for (int ni = 1; ni < 8; ni++) {
            mx0 = fmaxf(mx0, fmaxf(S[ni][0], S[ni][1]));
            mx1 = fmaxf(mx1, fmaxf(S[ni][2], S[ni][3]));
        }
        mx0 = fmaxf(mx0, __shfl_xor_sync(0xFFFFFFFFu, mx0, 1));
        mx0 = fmaxf(mx0, __shfl_xor_sync(0xFFFFFFFFu, mx0, 2));
        mx1 = fmaxf(mx1, __shfl_xor_sync(0xFFFFFFFFu, mx1, 1));
        mx1 = fmaxf(mx1, __shfl_xor_sync(0xFFFFFFFFu, mx1, 2));
        const float mn0 = fmaxf(m0, mx0), mn1 = fmaxf(m1, mx1);
        const float a0 = __expf(m0 - mn0), a1 = __expf(m1 - mn1);
        float s0 = 0.f, s1 = 0.f;
        #pragma unroll
        for (int ni = 0; ni < 8; ni++) {
            S[ni][0] = __expf(S[ni][0] - mn0);
            S[ni][1] = __expf(S[ni][1] - mn0);
            S[ni][2] = __expf(S[ni][2] - mn1);
            S[ni][3] = __expf(S[ni][3] - mn1);
            s0 += S[ni][0] + S[ni][1];
            s1 += S[ni][2] + S[ni][3];
        }
        s0 += __shfl_xor_sync(0xFFFFFFFFu, s0, 1);
        s0 += __shfl_xor_sync(0xFFFFFFFFu, s0, 2);
        s1 += __shfl_xor_sync(0xFFFFFFFFu, s1, 1);
        s1 += __shfl_xor_sync(0xFFFFFFFFu, s1, 2);
        l0 = l0 * a0 + s0;  l1 = l1 * a1 + s1;
        m0 = mn0;  m1 = mn1;

        #pragma unroll
        for (int ni = 0; ni < 16; ni++) {
            Of[ni][0] *= a0; Of[ni][1] *= a0;
            Of[ni][2] *= a1; Of[ni][3] *= a1;
        }

        uint32_t pf[4][4];
        #pragma unroll
        for (int kk2 = 0; kk2 < 4; kk2++) {
            pf[kk2][0] = packh2(S[2 * kk2][0],     S[2 * kk2][1]);
            pf[kk2][1] = packh2(S[2 * kk2][2],     S[2 * kk2][3]);
            pf[kk2][2] = packh2(S[2 * kk2 + 1][0], S[2 * kk2 + 1][1]);
            pf[kk2][3] = packh2(S[2 * kk2 + 1][2], S[2 * kk2 + 1][3]);
        }

        // O += P @ V : V frags via ldmatrix.trans on natural [k][d] tile.
        #pragma unroll
        for (int vp = 0; vp < 8; vp++) {
            #pragma unroll
            for (int kk2 = 0; kk2 < 4; kk2++) {
                uint32_t r0, r1, r2, r3;
                ldm4t(r0, r1, r2, r3,
                      vbase + (uint32_t)((kk2 * 16 + vkrow) * VLD +
                                         vp * 16 + vncol) * 2);
                uint32_t b0[2] = {r0, r1}, b1[2] = {r2, r3};
                mma_f16(Of[2 * vp],     pf[kk2], b0);
                mma_f16(Of[2 * vp + 1], pf[kk2], b1);
            }
        }
    }

    const float i0 = 1.f / l0, i1 = 1.f / l1;
    const int tok0 = b * SEQ + q0 + wid * 16 + gid;
    #pragma unroll
    for (int ni = 0; ni < 16; ni++) {
        const int col = h * HD + ni * 8 + 2 * tig;
        *(__half2*)(attnH + (size_t)tok0 * DMODEL + col) =
            __floats2half2_rn(Of[ni][0] * i0, Of[ni][1] * i0);
        *(__half2*)(attnH + (size_t)(tok0 + 8) * DMODEL + col) =
            __floats2half2_rn(Of[ni][2] * i1, Of[ni][3] * i1);
    }
}

// ---------------------------------------------------------------------------
extern "C" void kernel_launch(void* const* d_in, const int* in_sizes, int n_in,
                              void* d_out, int out_size)
{
    const float* hidden = (const float*)d_in[0];
    const float* cosT   = (const float*)d_in[1];
    const float* sinT   = (const float*)d_in[2];
    const float* Wqkv   = (const float*)d_in[3];
    const float* Wout   = (const float*)d_in[4];
    float* out = (float*)d_out;

    __half *qkvh, *Xh, *WqTh, *WoTh, *attnH;
    cudaGetSymbolAddress((void**)&qkvh,  g_qkvh);
    cudaGetSymbolAddress((void**)&Xh,    g_Xh);
    cudaGetSymbolAddress((void**)&WqTh,  g_WqTh);
    cudaGetSymbolAddress((void**)&WoTh,  g_WoTh);
    cudaGetSymbolAddress((void**)&attnH, g_attnH);

    cudaFuncSetAttribute(gemm_mma_f16<true>,
                         cudaFuncAttributeMaxDynamicSharedMemorySize, GEMM_SMEM);
    cudaFuncSetAttribute(gemm_mma_f16<false>,
                         cudaFuncAttributeMaxDynamicSharedMemorySize, GEMM_SMEM);
    cudaFuncSetAttribute(flash_mma,
                         cudaFuncAttributeMaxDynamicSharedMemorySize, FLASH_SMEM);

    // 0) fp16 conversions
    f32_to_f16_kernel<<<2048, 256>>>((const float4*)hidden, (__half2*)Xh,
                                     MTOK * DMODEL / 4);
    transpose_f16_kernel<<<dim3(QKVD / 32, DMODEL / 32), dim3(32, 8)>>>(
        Wqkv, WqTh, DMODEL, QKVD);
    transpose_f16_kernel<<<dim3(DMODEL / 32, DMODEL / 32), dim3(32, 8)>>>(
        Wout, WoTh, DMODEL, DMODEL);

    // 1) QKV projection (fp16 out)
    gemm_mma_f16<true><<<dim3(QKVD / 128, MTOK / 128), 128, GEMM_SMEM>>>(
        Xh, WqTh, qkvh, QKVD, DMODEL);

    // 2) RoPE in-place on qkvh
    rope_inplace_kernel<<<dim3(MTOK, 5), 256>>>(qkvh, cosT, sinT);

    // 3) Flash attention straight out of qkvh (trans-ldmatrix V)
    flash_mma<<<dim3(SEQ / 128, BATCH * NHEADS), 256, FLASH_SMEM>>>(
        qkvh, attnH);

    // 4) Output projection (fp32 out)
    gemm_mma_f16<false><<<dim3(DMODEL / 128, MTOK / 128), 128, GEMM_SMEM>>>(
        attnH, WoTh, out, DMODEL, DMODEL);
}

// round 14
// speedup vs baseline: 1.1923x; 1.0304x over previous
#include <cuda_runtime.h>
#include <cuda_fp16.h>
#include <math.h>
#include <stdint.h>

#define BATCH   2
#define SEQ     2048
#define DMODEL  4096
#define NHEADS  32
#define NKV     8
#define HD      128
#define QKVD    6144            // (32 + 2*8) * 128
#define MTOK    (BATCH * SEQ)   // 4096

// Scratch (allocation-free rule: __device__ globals)
__device__ __half g_qkvh [(size_t)MTOK * QKVD];
__device__ __half g_Xh   [(size_t)MTOK * DMODEL];
__device__ __half g_WqTh [(size_t)QKVD * DMODEL];
__device__ __half g_WoTh [(size_t)DMODEL * DMODEL];
__device__ __half g_attnH[(size_t)MTOK * DMODEL];

// ---------------------------------------------------------------------------
// Helpers (baseline PTX only)
// ---------------------------------------------------------------------------
__device__ __forceinline__ uint32_t s2u(const void* p) {
    uint32_t a;
    asm("{ .reg .u64 t; cvta.to.shared.u64 t, %1; cvt.u32.u64 %0, t; }"
        : "=r"(a) : "l"(p));
    return a;
}
__device__ __forceinline__ void cp_async16(uint32_t dst, const void* src) {
    asm volatile("cp.async.cg.shared.global [%0], [%1], 16;"
                 :: "r"(dst), "l"(src) : "memory");
}
__device__ __forceinline__ void mma_f16(float* c, const uint32_t* a,
                                        const uint32_t* b) {
    asm volatile(
        "mma.sync.aligned.m16n8k16.row.col.f32.f16.f16.f32 "
        "{%0,%1,%2,%3}, {%4,%5,%6,%7}, {%8,%9}, {%0,%1,%2,%3};"
        : "+f"(c[0]), "+f"(c[1]), "+f"(c[2]), "+f"(c[3])
        : "r"(a[0]), "r"(a[1]), "r"(a[2]), "r"(a[3]), "r"(b[0]), "r"(b[1]));
}
__device__ __forceinline__ void ldm4(uint32_t& r0, uint32_t& r1,
                                     uint32_t& r2, uint32_t& r3, uint32_t addr) {
    asm volatile("ldmatrix.sync.aligned.m8n8.x4.shared.b16 {%0,%1,%2,%3}, [%4];"
                 : "=r"(r0), "=r"(r1), "=r"(r2), "=r"(r3) : "r"(addr));
}
__device__ __forceinline__ void ldm4t(uint32_t& r0, uint32_t& r1,
                                      uint32_t& r2, uint32_t& r3, uint32_t addr) {
    asm volatile("ldmatrix.sync.aligned.m8n8.x4.trans.shared.b16 {%0,%1,%2,%3}, [%4];"
                 : "=r"(r0), "=r"(r1), "=r"(r2), "=r"(r3) : "r"(addr));
}
__device__ __forceinline__ uint32_t packh2(float x, float y) {
    __half2 h = __floats2half2_rn(x, y);
    return *(uint32_t*)&h;
}

// ---------------------------------------------------------------------------
// Prep kernels
// ---------------------------------------------------------------------------
__global__ void f32_to_f16_kernel(const float4* __restrict__ in,
                                  __half2* __restrict__ out, int n4) {
    for (int i = blockIdx.x * blockDim.x + threadIdx.x; i < n4;
         i += gridDim.x * blockDim.x) {
        float4 v = in[i];
        out[2 * i]     = __floats2half2_rn(v.x, v.y);
        out[2 * i + 1] = __floats2half2_rn(v.z, v.w);
    }
}

__global__ void transpose_f16_kernel(const float* __restrict__ in,
                                     __half* __restrict__ out, int R, int C) {
    __shared__ float t[32][33];
    int cb = blockIdx.x * 32, rb = blockIdx.y * 32;
    int tx = threadIdx.x, ty = threadIdx.y;
    #pragma unroll
    for (int i = 0; i < 4; i++)
        t[ty + i * 8][tx] = in[(size_t)(rb + ty + i * 8) * C + cb + tx];
    __syncthreads();
    #pragma unroll
    for (int i = 0; i < 4; i++)
        out[(size_t)(cb + ty + i * 8) * R + rb + tx] =
            __float2half_rn(t[tx][ty + i * 8]);
}

// ---------------------------------------------------------------------------
// fp16 mma.sync GEMM: C[M,N] = A[M,K] @ Bt[N,K]^T   (fp16, K-major)
// CTA tile 128x64, BK=32, 128 thr = 4 warps (2M x 2N), warp tile 64x32.
// FOUR CTAs per SM (independent sync domains, 16 warps/SM) -- flash-style
// latency hiding. 3-stage cp.async pipeline.
// ---------------------------------------------------------------------------
#define GLD   40                                  // smem stride in halves
#define GA_B  (128 * GLD * 2)                     // A bytes per stage (10240)
#define GB_B  (64 * GLD * 2)                      // B bytes per stage (5120)
#define GSTG  (GA_B + GB_B)                       // 15360
#define GEMM_SMEM (3 * GSTG)                      // 46080

template<bool HALF_OUT>
__global__ __launch_bounds__(128, 4) void gemm_mma_f16(
    const __half* __restrict__ A, const __half* __restrict__ Bt,
    void* __restrict__ Cv, int N, int K)
{
    extern __shared__ char dsm[];
    const int tid  = threadIdx.x;
    const int wid  = tid >> 5;
    const int lane = tid & 31;
    const int gid  = lane >> 2;
    const int tig  = lane & 3;
    const int wm   = (wid >> 1) * 64;   // 2 M-warp slots
    const int wn   = (wid & 1) * 32;    // 2 N-warp slots
    const int m0 = blockIdx.y * 128;
    const int n0 = blockIdx.x * 64;
    const uint32_t sb = s2u(dsm);

    const int lrow = ((lane >> 3) & 1) * 8 + (lane & 7);
    const int lcol = (lane >> 4) * 8;

    const __half* Ab = A  + (size_t)m0 * K;
    const __half* Bb = Bt + (size_t)n0 * K;
    const int NC = K >> 5;

    // A tile 128x32 halves = 512 x16B / 128 thr = 4; B 64x32 = 256 / 128 = 2.
    #define GLOAD(kc, st)                                                      \
    {                                                                          \
        uint32_t sbase = sb + (st) * GSTG;                                     \
        _Pragma("unroll")                                                      \
        for (int i = 0; i < 4; i++) {                                          \
            int idx = i * 128 + tid;                                           \
            int r = idx >> 2, c8 = idx & 3;                                    \
            cp_async16(sbase + (uint32_t)(r * GLD + c8 * 8) * 2,               \
                       Ab + (size_t)r * K + (kc) * 32 + c8 * 8);               \
        }                                                                      \
        _Pragma("unroll")                                                      \
        for (int i = 0; i < 2; i++) {                                          \
            int idx = i * 128 + tid;                                           \
            int r = idx >> 2, c8 = idx & 3;                                    \
            cp_async16(sbase + GA_B + (uint32_t)(r * GLD + c8 * 8) * 2,        \
                       Bb + (size_t)r * K + (kc) * 32 + c8 * 8);               \
        }                                                                      \
        asm volatile("cp.async.commit_group;" ::: "memory");                   \
    }

    float acc[4][4][4];
    #pragma unroll
    for (int mi = 0; mi < 4; mi++)
        #pragma unroll
        for (int ni = 0; ni < 4; ni++)
            #pragma unroll
            for (int q = 0; q < 4; q++) acc[mi][ni][q] = 0.f;

    GLOAD(0, 0);
    GLOAD(1, 1);

    for (int kc = 0; kc < NC; kc++) {
        if (kc + 1 < NC) asm volatile("cp.async.wait_group 1;" ::: "memory");
        else             asm volatile("cp.async.wait_group 0;" ::: "memory");
        __syncthreads();
        if (kc + 2 < NC) GLOAD(kc + 2, (kc + 2) % 3);

        const uint32_t sA = sb + (kc % 3) * GSTG;
        const uint32_t sB = sA + GA_B;

        #pragma unroll
        for (int ks = 0; ks < 2; ks++) {
            const int k0h = ks * 16;
            uint32_t af[4][4], bf[4][2];
            #pragma unroll
            for (int mi = 0; mi < 4; mi++)
                ldm4(af[mi][0], af[mi][1], af[mi][2], af[mi][3],
                     sA + (uint32_t)((wm + mi * 16 + lrow) * GLD + k0h + lcol) * 2);
            #pragma unroll
            for (int np = 0; np < 2; np++) {
                uint32_t r0, r1, r2, r3;
                ldm4(r0, r1, r2, r3,
                     sB + (uint32_t)((wn + np * 16 + lrow) * GLD + k0h + lcol) * 2);
                bf[2 * np][0] = r0;     bf[2 * np][1] = r2;
                bf[2 * np + 1][0] = r1; bf[2 * np + 1][1] = r3;
            }
            #pragma unroll
            for (int mi = 0; mi < 4; mi++)
                #pragma unroll
                for (int ni = 0; ni < 4; ni++)
                    mma_f16(acc[mi][ni], af[mi], bf[ni]);
        }
    }

    #pragma unroll
    for (int mi = 0; mi < 4; mi++) {
        const int r0 = m0 + wm + mi * 16 + gid;
        #pragma unroll
        for (int ni = 0; ni < 4; ni++) {
            const int c = n0 + wn + ni * 8 + 2 * tig;
            if (HALF_OUT) {
                __half* C = (__half*)Cv;
                *(__half2*)(C + (size_t)r0 * N + c) =
                    __floats2half2_rn(acc[mi][ni][0], acc[mi][ni][1]);
                *(__half2*)(C + (size_t)(r0 + 8) * N + c) =
                    __floats2half2_rn(acc[mi][ni][2], acc[mi][ni][3]);
            } else {
                float* C = (float*)Cv;
                *(float2*)(C + (size_t)r0 * N + c) =
                    make_float2(acc[mi][ni][0], acc[mi][ni][1]);
                *(float2*)(C + (size_t)(r0 + 8) * N + c) =
                    make_float2(acc[mi][ni][2], acc[mi][ni][3]);
            }
        }
    }
}

// ---------------------------------------------------------------------------
// RoPE in-place on qkvh (Q heads 0..31, K heads 32..39), half2-vectorized.
// ---------------------------------------------------------------------------
__global__ void rope_inplace_kernel(__half* __restrict__ qkv,
                                    const float* __restrict__ cosT,
                                    const float* __restrict__ sinT)
{
    const int token = blockIdx.x;
    const int head  = blockIdx.y * 8 + (threadIdx.x >> 5);  // 0..39
    const int d2    = (threadIdx.x & 31) * 2;               // 0..62
    const int s = token & (SEQ - 1);

    __half* p = qkv + (size_t)token * QKVD + head * HD;
    const float2 c  = *(const float2*)(cosT + s * HD + d2);
    const float2 sn = *(const float2*)(sinT + s * HD + d2);
    const __half2 x1h = *(__half2*)(p + d2);
    const __half2 x2h = *(__half2*)(p + d2 + 64);
    const float x1a = __low2float(x1h), x1b = __high2float(x1h);
    const float x2a = __low2float(x2h), x2b = __high2float(x2h);
    *(__half2*)(p + d2) =
        __floats2half2_rn(x1a * c.x - x2a * sn.x, x1b * c.y - x2b * sn.y);
    *(__half2*)(p + d2 + 64) =
        __floats2half2_rn(x2a * c.x + x1a * sn.x, x2b * c.y + x1b * sn.y);
}

// ---------------------------------------------------------------------------
// Flash attention, mma.sync fp16, ldmatrix fragment fetch, direct from qkvh.
// Base-2 online softmax (log2e folded into scale). BQ=128, BK=64, 8 warps.
// ---------------------------------------------------------------------------
#define QLD 136
#define KLD 136
#define VLD 136
#define K_TILE_B (64 * KLD * 2)
#define V_TILE_B (64 * VLD * 2)
#define STAGE_B  (K_TILE_B + V_TILE_B)
#define FLASH_SMEM (2 * STAGE_B)

__global__ __launch_bounds__(256) void flash_mma(
    const __half* __restrict__ qkv, __half* __restrict__ attnH)
{
    extern __shared__ char dsm[];
    const int tid = threadIdx.x;
    const int wid = tid >> 5, lane = tid & 31;
    const int gid = lane >> 2, tig = lane & 3;
    const int lrow = ((lane >> 3) & 1) * 8 + (lane & 7);
    const int lcol = (lane >> 4) * 8;
    const int qt = (gridDim.x - 1) - blockIdx.x;
    const int bh = blockIdx.y;
    const int b = bh >> 5, h = bh & 31, kvh = h >> 2;
    const int q0 = qt * 128;
    const uint32_t sb = s2u(dsm);
    const float sc2 = 0.08838834764831845f * 1.4426950408889634f; // scale*log2e

    const __half* Qg = qkv + ((size_t)(b * SEQ + q0)) * QKVD + h * HD;
    const __half* Kg = qkv + (size_t)(b * SEQ) * QKVD + (NHEADS + kvh) * HD;
    const __half* Vg = qkv + (size_t)(b * SEQ) * QKVD + (NHEADS + NKV + kvh) * HD;

    #pragma unroll
    for (int i = 0; i < 8; i++) {
        int idx = i * 256 + tid;
        int r = idx >> 4, c = idx & 15;
        cp_async16(sb + (uint32_t)(r * QLD + c * 8) * 2,
                   Qg + (size_t)r * QKVD + c * 8);
    }
    asm volatile("cp.async.commit_group;" ::: "memory");
    asm volatile("cp.async.wait_group 0;" ::: "memory");
    __syncthreads();

    uint32_t qf[8][4];
    #pragma unroll
    for (int kk = 0; kk < 8; kk++)
        ldm4(qf[kk][0], qf[kk][1], qf[kk][2], qf[kk][3],
             sb + (uint32_t)((wid * 16 + lrow) * QLD + kk * 16 + lcol) * 2);
    __syncthreads();

    #define LOADKV(kt, st)                                                     \
    {                                                                          \
        const int k0_ = (kt) * 64;                                             \
        uint32_t base_ = sb + (st) * STAGE_B;                                  \
        _Pragma("unroll")                                                      \
        for (int i_ = 0; i_ < 2; i_++) {                                       \
            int idx_ = i_ * 256 + tid;                                         \
            int r_ = idx_ >> 3, c_ = idx_ & 7;                                 \
            cp_async16(base_ + (uint32_t)(r_ * KLD + c_ * 16) * 2,             \
                       Kg + (size_t)(k0_ + r_) * QKVD + c_ * 16);              \
            cp_async16(base_ + (uint32_t)(r_ * KLD + c_ * 16 + 8) * 2,        \
                       Kg + (size_t)(k0_ + r_) * QKVD + c_ * 16 + 8);          \
        }                                                                      \
        _Pragma("unroll")                                                      \
        for (int i_ = 0; i_ < 2; i_++) {                                       \
            int idx_ = i_ * 256 + tid;                                         \
            int r_ = idx_ >> 3, c_ = idx_ & 7;                                 \
            cp_async16(base_ + K_TILE_B + (uint32_t)(r_ * VLD + c_ * 16) * 2,  \
                       Vg + (size_t)(k0_ + r_) * QKVD + c_ * 16);              \
            cp_async16(base_ + K_TILE_B + (uint32_t)(r_ * VLD + c_ * 16 + 8) * 2, \
                       Vg + (size_t)(k0_ + r_) * QKVD + c_ * 16 + 8);          \
        }                                                                      \
        asm volatile("cp.async.commit_group;" ::: "memory");                   \
    }

    float Of[16][4];
    #pragma unroll
    for (int ni = 0; ni < 16; ni++)
        #pragma unroll
        for (int q = 0; q < 4; q++) Of[ni][q] = 0.f;
    float m0 = -INFINITY, m1 = -INFINITY, l0 = 0.f, l1 = 0.f;
    const int nkt = 2 * qt + 2;

    LOADKV(0, 0);

    const int vkrow = ((lane >> 3) & 1) * 8 + (lane & 7);
    const int vncol = (lane >> 4) * 8;

    for (int kt = 0; kt < nkt; kt++) {
        const int s = kt & 1;
        asm volatile("cp.async.wait_group 0;" ::: "memory");
        __syncthreads();
        if (kt + 1 < nkt) LOADKV(kt + 1, s ^ 1);

        const uint32_t kbase = sb + s * STAGE_B;
        const uint32_t vbase = kbase + K_TILE_B;
        const int k0 = kt * 64;

        float S[8][4];
        #pragma unroll
        for (int ni = 0; ni < 8; ni++)
            S[ni][0] = S[ni][1] = S[ni][2] = S[ni][3] = 0.f;
        #pragma unroll
        for (int np = 0; np < 4; np++) {
            #pragma unroll
            for (int kk = 0; kk < 8; kk++) {
                uint32_t r0, r1, r2, r3;
                ldm4(r0, r1, r2, r3,
                     kbase + (uint32_t)((np * 16 + lrow) * KLD + kk * 16 + lcol) * 2);
                uint32_t b0[2] = {r0, r2}, b1[2] = {r1, r3};
                mma_f16(S[2 * np],     qf[kk], b0);
                mma_f16(S[2 * np + 1], qf[kk], b1);
            }
        }

        const int row0 = q0 + wid * 16 + gid, row1 = row0 + 8;
        #pragma unroll
        for (int ni = 0; ni < 8; ni++) {
            const int col = k0 + ni * 8 + 2 * tig;
            S[ni][0] = (col     <= row0) ? S[ni][0] * sc2 : -1e30f;
            S[ni][1] = (col + 1 <= row0) ? S[ni][1] * sc2 : -1e30f;
            S[ni][2] = (col     <= row1) ? S[ni][2] * sc2 : -1e30f;
            S[ni][3] = (col + 1 <= row1) ? S[ni][3] * sc2 : -1e30f;
        }

        float mx0 = fmaxf(S[0][0], S[0][1]), mx1 = fmaxf(S[0][2], S[0][3]);
        #pragma unroll
        for (int ni = 1; ni < 8; ni++) {
            mx0 = fmaxf(mx0, fmaxf(S[ni][0], S[ni][1]));
            mx1 = fmaxf(mx1, fmaxf(S[ni][2], S[ni][3]));
        }
        mx0 = fmaxf(mx0, __shfl_xor_sync(0xFFFFFFFFu, mx0, 1));
        mx0 = fmaxf(mx0, __shfl_xor_sync(0xFFFFFFFFu, mx0, 2));
        mx1 = fmaxf(mx1, __shfl_xor_sync(0xFFFFFFFFu, mx1, 1));
        mx1 = fmaxf(mx1, __shfl_xor_sync(0xFFFFFFFFu, mx1, 2));
        const float mn0 = fmaxf(m0, mx0), mn1 = fmaxf(m1, mx1);
        const float a0 = exp2f(m0 - mn0), a1 = exp2f(m1 - mn1);
        float s0 = 0.f, s1 = 0.f;
        #pragma unroll
        for (int ni = 0; ni < 8; ni++) {
            S[ni][0] = exp2f(S[ni][0] - mn0);
            S[ni][1] = exp2f(S[ni][1] - mn0);
            S[ni][2] = exp2f(S[ni][2] - mn1);
            S[ni][3] = exp2f(S[ni][3] - mn1);
            s0 += S[ni][0] + S[ni][1];
            s1 += S[ni][2] + S[ni][3];
        }
        s0 += __shfl_xor_sync(0xFFFFFFFFu, s0, 1);
        s0 += __shfl_xor_sync(0xFFFFFFFFu, s0, 2);
        s1 += __shfl_xor_sync(0xFFFFFFFFu, s1, 1);
        s1 += __shfl_xor_sync(0xFFFFFFFFu, s1, 2);
        l0 = l0 * a0 + s0;  l1 = l1 * a1 + s1;
        m0 = mn0;  m1 = mn1;

        #pragma unroll
        for (int ni = 0; ni < 16; ni++) {
            Of[ni][0] *= a0; Of[ni][1] *= a0;
            Of[ni][2] *= a1; Of[ni][3] *= a1;
        }

        uint32_t pf[4][4];
        #pragma unroll
        for (int kk2 = 0; kk2 < 4; kk2++) {
            pf[kk2][0] = packh2(S[2 * kk2][0],     S[2 * kk2][1]);
            pf[kk2][1] = packh2(S[2 * kk2][2],     S[2 * kk2][3]);
            pf[kk2][2] = packh2(S[2 * kk2 + 1][0], S[2 * kk2 + 1][1]);
            pf[kk2][3] = packh2(S[2 * kk2 + 1][2], S[2 * kk2 + 1][3]);
        }

        #pragma unroll
        for (int vp = 0; vp < 8; vp++) {
            #pragma unroll
            for (int kk2 = 0; kk2 < 4; kk2++) {
                uint32_t r0, r1, r2, r3;
                ldm4t(r0, r1, r2, r3,
                      vbase + (uint32_t)((kk2 * 16 + vkrow) * VLD +
                                         vp * 16 + vncol) * 2);
                uint32_t b0[2] = {r0, r1}, b1[2] = {r2, r3};
                mma_f16(Of[2 * vp],     pf[kk2], b0);
                mma_f16(Of[2 * vp + 1], pf[kk2], b1);
            }
        }
    }

    const float i0 = 1.f / l0, i1 = 1.f / l1;
    const int tok0 = b * SEQ + q0 + wid * 16 + gid;
    #pragma unroll
    for (int ni = 0; ni < 16; ni++) {
        const int col = h * HD + ni * 8 + 2 * tig;
        *(__half2*)(attnH + (size_t)tok0 * DMODEL + col) =
            __floats2half2_rn(Of[ni][0] * i0, Of[ni][1] * i0);
        *(__half2*)(attnH + (size_t)(tok0 + 8) * DMODEL + col) =
            __floats2half2_rn(Of[ni][2] * i1, Of[ni][3] * i1);
    }
}

// ---------------------------------------------------------------------------
extern "C" void kernel_launch(void* const* d_in, const int* in_sizes, int n_in,
                              void* d_out, int out_size)
{
    const float* hidden = (const float*)d_in[0];
    const float* cosT   = (const float*)d_in[1];
    const float* sinT   = (const float*)d_in[2];
    const float* Wqkv   = (const float*)d_in[3];
    const float* Wout   = (const float*)d_in[4];
    float* out = (float*)d_out;

    __half *qkvh, *Xh, *WqTh, *WoTh, *attnH;
    cudaGetSymbolAddress((void**)&qkvh,  g_qkvh);
    cudaGetSymbolAddress((void**)&Xh,    g_Xh);
    cudaGetSymbolAddress((void**)&WqTh,  g_WqTh);
    cudaGetSymbolAddress((void**)&WoTh,  g_WoTh);
    cudaGetSymbolAddress((void**)&attnH, g_attnH);

    cudaFuncSetAttribute(gemm_mma_f16<true>,
                         cudaFuncAttributeMaxDynamicSharedMemorySize, GEMM_SMEM);
    cudaFuncSetAttribute(gemm_mma_f16<false>,
                         cudaFuncAttributeMaxDynamicSharedMemorySize, GEMM_SMEM);
    cudaFuncSetAttribute(flash_mma,
                         cudaFuncAttributeMaxDynamicSharedMemorySize, FLASH_SMEM);

    // 0) fp16 conversions
    f32_to_f16_kernel<<<2048, 256>>>((const float4*)hidden, (__half2*)Xh,
                                     MTOK * DMODEL / 4);
    transpose_f16_kernel<<<dim3(QKVD / 32, DMODEL / 32), dim3(32, 8)>>>(
        Wqkv, WqTh, DMODEL, QKVD);
    transpose_f16_kernel<<<dim3(DMODEL / 32, DMODEL / 32), dim3(32, 8)>>>(
        Wout, WoTh, DMODEL, DMODEL);

    // 1) QKV projection (fp16 out), CTA 128x64, 4 warps, 4 CTAs/SM
    gemm_mma_f16<true><<<dim3(QKVD / 64, MTOK / 128), 128, GEMM_SMEM>>>(
        Xh, WqTh, qkvh, QKVD, DMODEL);

    // 2) RoPE in-place on qkvh
    rope_inplace_kernel<<<dim3(MTOK, 5), 256>>>(qkvh, cosT, sinT);

    // 3) Flash attention straight out of qkvh
    flash_mma<<<dim3(SEQ / 128, BATCH * NHEADS), 256, FLASH_SMEM>>>(
        qkvh, attnH);

    // 4) Output projection (fp32 out)
    gemm_mma_f16<false><<<dim3(DMODEL / 64, MTOK / 128), 128, GEMM_SMEM>>>(
        attnH, WoTh, out, DMODEL, DMODEL);
}